// round 4
// baseline (speedup 1.0000x reference)
#include <cuda_runtime.h>
#include <math.h>

#define BB 4096
#define NN 64
#define XS 408     // sh_x stride: cols 0..15=z, 16..271=h, 272..399=c
#define QS 68      // q/k/v/at/clat stride

// smem (floats): x 26112 | WC 12800 | q 4352 | k 4352 | v 4352 | at 4352 = 56320
#define OFF_X  0
#define OFF_WC 26112
#define OFF_Q  38912
#define OFF_K  43264
#define OFF_V  47616
#define OFF_AT 51968
#define SMEM_FLOATS 56320

typedef unsigned long long ull;

__device__ __forceinline__ ull pk(float a, float b) {
    ull r; asm("mov.b64 %0, {%1, %2};" : "=l"(r) : "f"(a), "f"(b)); return r;
}
__device__ __forceinline__ void upk(ull v, float& a, float& b) {
    asm("mov.b64 {%0, %1}, %2;" : "=f"(a), "=f"(b) : "l"(v));
}
#define FMAX2(acc, a, b) asm("fma.rn.f32x2 %0, %1, %2, %0;" : "+l"(acc) : "l"(a), "l"(b))

__device__ __forceinline__ float wsum32(float v) {
    #pragma unroll
    for (int m = 16; m > 0; m >>= 1) v += __shfl_xor_sync(0xffffffffu, v, m);
    return v;
}
__device__ __forceinline__ float wmax32(float v) {
    #pragma unroll
    for (int m = 16; m > 0; m >>= 1) v = fmaxf(v, __shfl_xor_sync(0xffffffffu, v, m));
    return v;
}

__global__ __launch_bounds__(512, 1)
void memetic_fused_kernel(
    const float* __restrict__ h, const float* __restrict__ u, const float* __restrict__ z,
    const float* __restrict__ qd_down, const float* __restrict__ qd_up,
    const float* __restrict__ kd_down, const float* __restrict__ kd_up,
    const float* __restrict__ vd_down, const float* __restrict__ vd_up,
    const float* __restrict__ od_down, const float* __restrict__ od_up,
    const float* __restrict__ ug_w, const float* __restrict__ ug_b,
    const float* __restrict__ cand_w, const float* __restrict__ cand_b,
    const float* __restrict__ eta_logit,
    float* __restrict__ out_c, float* __restrict__ out_z,
    float* __restrict__ out_attn, float* __restrict__ out_q,
    float* __restrict__ out_k, float* __restrict__ out_v)
{
    extern __shared__ float sm[];
    float* shx  = sm + OFF_X;
    float* swc  = sm + OFF_WC;
    float* sq   = sm + OFF_Q;
    float* sk   = sm + OFF_K;
    float* sv   = sm + OFF_V;
    float* sat  = sm + OFF_AT;
    float* sclat = sq;          // alias: q dead after C1
    float* sred  = sv;          // alias: v+at dead after C2 (6144 floats needed)
    float* sgc   = sk;          // alias: k dead after C1

    const int b    = blockIdx.x;
    const int tid  = threadIdx.x;
    const int wid  = tid >> 5;
    const int lane = tid & 31;
    const float NEG_INF = __int_as_float(0xff800000);

    // ---------------- Phase A: stage h, z, gate weights ----------------
    {
        const float4* hb4 = reinterpret_cast<const float4*>(h + (size_t)b * (NN * 256));
        #pragma unroll
        for (int c = 0; c < 4; c++) {
            int row = (wid << 2) + c;
            #pragma unroll
            for (int it = 0; it < 2; it++) {
                int c4 = lane + (it << 5);                       // float4 col
                float4 v4 = hb4[row * 64 + c4];
                *reinterpret_cast<float4*>(shx + row * XS + 16 + (c4 << 2)) = v4;
            }
        }
        const float* zb = z + (size_t)b * (NN * 16);
        for (int i = tid; i < NN * 16; i += 512)
            shx[(i >> 4) * XS + (i & 15)] = zb[i];
        const float4* ug4 = reinterpret_cast<const float4*>(ug_w);
        const float4* cd4 = reinterpret_cast<const float4*>(cand_w);
        float4* wc4 = reinterpret_cast<float4*>(swc);
        for (int i4 = tid; i4 < 3200; i4 += 512) {
            int r = i4 >> 3, jq = i4 & 7;
            wc4[i4] = (jq < 4) ? __ldg(ug4 + r * 4 + jq) : __ldg(cd4 + r * 4 + (jq - 4));
        }
    }
    __syncthreads();

    // ---------------- Phase B: q, k, v (warp per token, 4 tokens/warp) ----------------
    {
        const float* ub = u + (size_t)b * (NN * 128);
        const float4* qdd4 = reinterpret_cast<const float4*>(qd_down);
        const float4* kdd4 = reinterpret_cast<const float4*>(kd_down);
        const float4* vdd4 = reinterpret_cast<const float4*>(vd_down);
        for (int c0 = 0; c0 < 4; c0++) {
            const int t = (wid << 2) + c0;
            float q0 = 0.f, q1 = 0.f, q2 = 0.f, q3 = 0.f;
            for (int i = lane; i < 272; i += 32) {
                int col = (i < 256) ? (16 + i) : (i - 256);
                float x = shx[t * XS + col];
                float4 wv = __ldg(qdd4 + i);
                q0 += x * wv.x; q1 += x * wv.y; q2 += x * wv.z; q3 += x * wv.w;
            }
            q0 = wsum32(q0); q1 = wsum32(q1); q2 = wsum32(q2); q3 = wsum32(q3);
            float k0 = 0.f, k1 = 0.f, k2 = 0.f, k3 = 0.f;
            float v0 = 0.f, v1 = 0.f, v2 = 0.f, v3 = 0.f;
            #pragma unroll
            for (int it = 0; it < 4; it++) {
                int i = lane + it * 32;
                float x = __ldg(ub + t * 128 + i);
                float4 kw = __ldg(kdd4 + i);
                float4 vw = __ldg(vdd4 + i);
                k0 += x * kw.x; k1 += x * kw.y; k2 += x * kw.z; k3 += x * kw.w;
                v0 += x * vw.x; v1 += x * vw.y; v2 += x * vw.z; v3 += x * vw.w;
            }
            k0 = wsum32(k0); k1 = wsum32(k1); k2 = wsum32(k2); k3 = wsum32(k3);
            v0 = wsum32(v0); v1 = wsum32(v1); v2 = wsum32(v2); v3 = wsum32(v3);
            const size_t tok = (size_t)(b * NN + t);
            #pragma unroll
            for (int s = 0; s < 2; s++) {
                int d = lane + (s << 5);
                float qv = 0.25f * (q0 * __ldg(qd_up + d)       + q1 * __ldg(qd_up + 64 + d)
                                  + q2 * __ldg(qd_up + 128 + d) + q3 * __ldg(qd_up + 192 + d));
                float kv = 0.25f * (k0 * __ldg(kd_up + d)       + k1 * __ldg(kd_up + 64 + d)
                                  + k2 * __ldg(kd_up + 128 + d) + k3 * __ldg(kd_up + 192 + d));
                float vv = 0.25f * (v0 * __ldg(vd_up + d)       + v1 * __ldg(vd_up + 64 + d)
                                  + v2 * __ldg(vd_up + 128 + d) + v3 * __ldg(vd_up + 192 + d));
                sq[t * QS + d] = qv;
                sk[t * QS + d] = kv;
                sv[t * QS + d] = vv;
                out_q[tok * 64 + d] = qv;
                out_k[tok * 64 + d] = kv;
                out_v[tok * 64 + d] = vv;
            }
        }
    }
    __syncthreads();

    // ---------------- Phase C1: QK scores; 8 tiles of 16n x 32m, 2-warp k-split ----------------
    {
        const int tile = wid >> 1, ks = wid & 1;
        const int n0 = (tile >> 1) * 16 + (lane & 3) * 4;
        const int m0 = (tile & 1) * 32 + (lane >> 2) * 4;
        ull acc[4][4];
        #pragma unroll
        for (int a = 0; a < 4; a++)
            #pragma unroll
            for (int bb = 0; bb < 4; bb++) acc[a][bb] = 0ull;
        const int dbase = ks << 5;
        #pragma unroll
        for (int s = 0; s < 8; s++) {
            const int dd = dbase + (s << 2);
            float4 q4[4], k4[4];
            #pragma unroll
            for (int a = 0; a < 4; a++)
                q4[a] = *reinterpret_cast<const float4*>(sq + (n0 + a) * QS + dd);
            #pragma unroll
            for (int bb = 0; bb < 4; bb++)
                k4[bb] = *reinterpret_cast<const float4*>(sk + (m0 + bb) * QS + dd);
            #pragma unroll
            for (int a = 0; a < 4; a++) {
                ull qlo = pk(q4[a].x, q4[a].y), qhi = pk(q4[a].z, q4[a].w);
                #pragma unroll
                for (int bb = 0; bb < 4; bb++) {
                    FMAX2(acc[a][bb], qlo, pk(k4[bb].x, k4[bb].y));
                    FMAX2(acc[a][bb], qhi, pk(k4[bb].z, k4[bb].w));
                }
            }
        }
        float sc[4][4];
        #pragma unroll
        for (int a = 0; a < 4; a++)
            #pragma unroll
            for (int bb = 0; bb < 4; bb++) {
                float lo, hi; upk(acc[a][bb], lo, hi); sc[a][bb] = lo + hi;
            }
        if (ks == 1) {
            #pragma unroll
            for (int a = 0; a < 4; a++)
                *reinterpret_cast<float4*>(sat + (n0 + a) * QS + m0) =
                    make_float4(sc[a][0], sc[a][1], sc[a][2], sc[a][3]);
        }
        __syncthreads();
        if (ks == 0) {
            #pragma unroll
            for (int a = 0; a < 4; a++) {
                float4 p = *reinterpret_cast<const float4*>(sat + (n0 + a) * QS + m0);
                float r0 = (sc[a][0] + p.x) * 0.125f;
                float r1 = (sc[a][1] + p.y) * 0.125f;
                float r2 = (sc[a][2] + p.z) * 0.125f;
                float r3 = (sc[a][3] + p.w) * 0.125f;
                int n = n0 + a;
                if (n == m0    ) r0 = NEG_INF;
                if (n == m0 + 1) r1 = NEG_INF;
                if (n == m0 + 2) r2 = NEG_INF;
                if (n == m0 + 3) r3 = NEG_INF;
                *reinterpret_cast<float4*>(sat + n * QS + m0) = make_float4(r0, r1, r2, r3);
            }
        }
        __syncthreads();
    }

    // ---------------- Phase C1b: softmax (warp per 4 rows) ----------------
    {
        #pragma unroll
        for (int rr = 0; rr < 4; rr++) {
            int n = (wid << 2) + rr;
            float s0 = sat[n * QS + lane];
            float s1 = sat[n * QS + lane + 32];
            float mx = wmax32(fmaxf(s0, s1));
            float e0 = __expf(s0 - mx), e1 = __expf(s1 - mx);
            float inv = 1.f / wsum32(e0 + e1);
            float a0 = e0 * inv, a1 = e1 * inv;
            sat[n * QS + lane]      = a0;
            sat[n * QS + lane + 32] = a1;
            size_t tk = (size_t)(b * NN + n) * 64;
            out_attn[tk + lane]      = a0;
            out_attn[tk + lane + 32] = a1;
        }
    }
    __syncthreads();

    // ---------------- Phase C2: c_latent = attn @ v; same tiling, k-split over m ----------------
    {
        const int tile = wid >> 1, ks = wid & 1;
        const int n0 = (tile >> 1) * 16 + (lane & 3) * 4;
        const int d0 = (tile & 1) * 32 + (lane >> 2) * 4;
        ull acc[4][2];
        #pragma unroll
        for (int a = 0; a < 4; a++) { acc[a][0] = 0ull; acc[a][1] = 0ull; }
        const int mbase = ks << 5;
        #pragma unroll
        for (int s = 0; s < 8; s++) {
            const int mm = mbase + (s << 2);
            float ar[4][4];
            #pragma unroll
            for (int a = 0; a < 4; a++) {
                float4 t4 = *reinterpret_cast<const float4*>(sat + (n0 + a) * QS + mm);
                ar[a][0] = t4.x; ar[a][1] = t4.y; ar[a][2] = t4.z; ar[a][3] = t4.w;
            }
            #pragma unroll
            for (int ss = 0; ss < 4; ss++) {
                float4 v4 = *reinterpret_cast<const float4*>(sv + (mm + ss) * QS + d0);
                ull vlo = pk(v4.x, v4.y), vhi = pk(v4.z, v4.w);
                #pragma unroll
                for (int a = 0; a < 4; a++) {
                    ull ad = pk(ar[a][ss], ar[a][ss]);
                    FMAX2(acc[a][0], ad, vlo);
                    FMAX2(acc[a][1], ad, vhi);
                }
            }
        }
        if (ks == 1) {
            #pragma unroll
            for (int a = 0; a < 4; a++) {
                float x0, x1, x2, x3;
                upk(acc[a][0], x0, x1); upk(acc[a][1], x2, x3);
                *reinterpret_cast<float4*>(sclat + (n0 + a) * QS + d0) = make_float4(x0, x1, x2, x3);
            }
        }
        __syncthreads();
        if (ks == 0) {
            #pragma unroll
            for (int a = 0; a < 4; a++) {
                float4 p = *reinterpret_cast<const float4*>(sclat + (n0 + a) * QS + d0);
                float x0, x1, x2, x3;
                upk(acc[a][0], x0, x1); upk(acc[a][1], x2, x3);
                *reinterpret_cast<float4*>(sclat + (n0 + a) * QS + d0) =
                    make_float4(x0 + p.x, x1 + p.y, x2 + p.z, x3 + p.w);
            }
        }
        __syncthreads();
    }

    // ---------------- Phase C3: rank-4 output projection (warp per token) ----------------
    {
        const float4* odd4 = reinterpret_cast<const float4*>(od_down);
        float4 o0 = __ldg(odd4 + lane);
        float4 o1 = __ldg(odd4 + lane + 32);
        for (int c0 = 0; c0 < 4; c0++) {
            int t = (wid << 2) + c0;
            float ca = sclat[t * QS + lane];
            float cb = sclat[t * QS + lane + 32];
            float r0 = wsum32(ca * o0.x + cb * o1.x);
            float r1 = wsum32(ca * o0.y + cb * o1.y);
            float r2 = wsum32(ca * o0.z + cb * o1.z);
            float r3 = wsum32(ca * o0.w + cb * o1.w);
            size_t tk = (size_t)(b * NN + t) * 128;
            #pragma unroll
            for (int s = 0; s < 4; s++) {
                int j = lane + (s << 5);
                float cv = 0.25f * (r0 * __ldg(od_up + j)       + r1 * __ldg(od_up + 128 + j)
                                  + r2 * __ldg(od_up + 256 + j) + r3 * __ldg(od_up + 384 + j));
                shx[t * XS + 272 + j] = cv;
                out_c[tk + j] = cv;
            }
        }
    }
    __syncthreads();

    // ---------------- Phase D: gate/cand matmuls; 4 tiles (32tok x 16out), 4-warp k-split ----------------
    {
        const int ip   = wid & 3;
        const int tile = wid >> 2;
        const int t0   = (tile >> 1) * 32 + (lane & 7) * 4;
        const int j0   = (tile & 1) * 16 + (lane >> 3) * 4;
        ull acc[4][2];
        #pragma unroll
        for (int c = 0; c < 4; c++) { acc[c][0] = 0ull; acc[c][1] = 0ull; }
        const int ibase = ip * 100;
        #pragma unroll 5
        for (int s = 0; s < 25; s++) {
            const int i0 = ibase + (s << 2);
            float xr[4][4];
            #pragma unroll
            for (int c = 0; c < 4; c++) {
                float4 x4 = *reinterpret_cast<const float4*>(shx + (t0 + c) * XS + i0);
                xr[c][0] = x4.x; xr[c][1] = x4.y; xr[c][2] = x4.z; xr[c][3] = x4.w;
            }
            #pragma unroll
            for (int r = 0; r < 4; r++) {
                float4 w4 = *reinterpret_cast<const float4*>(swc + (i0 + r) * 32 + j0);
                ull wlo = pk(w4.x, w4.y), whi = pk(w4.z, w4.w);
                #pragma unroll
                for (int c = 0; c < 4; c++) {
                    ull xd = pk(xr[c][r], xr[c][r]);
                    FMAX2(acc[c][0], xd, wlo);
                    FMAX2(acc[c][1], xd, whi);
                }
            }
        }
        __syncthreads();   // v/at fully dead -> sred safe
        if (ip != 0) {
            float* dst = sred + (tile * 3 + (ip - 1)) * 512 + lane * 16;
            #pragma unroll
            for (int c = 0; c < 4; c++) {
                float x0, x1, x2, x3;
                upk(acc[c][0], x0, x1); upk(acc[c][1], x2, x3);
                *reinterpret_cast<float4*>(dst + (c << 2)) = make_float4(x0, x1, x2, x3);
            }
        }
        __syncthreads();
        if (ip == 0) {
            float f[4][4];
            #pragma unroll
            for (int c = 0; c < 4; c++) {
                upk(acc[c][0], f[c][0], f[c][1]); upk(acc[c][1], f[c][2], f[c][3]);
            }
            #pragma unroll
            for (int s = 0; s < 3; s++) {
                const float* src = sred + (tile * 3 + s) * 512 + lane * 16;
                #pragma unroll
                for (int c = 0; c < 4; c++) {
                    float4 p = *reinterpret_cast<const float4*>(src + (c << 2));
                    f[c][0] += p.x; f[c][1] += p.y; f[c][2] += p.z; f[c][3] += p.w;
                }
            }
            #pragma unroll
            for (int d = 0; d < 4; d++) {
                int j = j0 + d;
                float bias = (j < 16) ? __ldg(ug_b + j) : __ldg(cand_b + j - 16);
                #pragma unroll
                for (int c = 0; c < 4; c++)
                    sgc[(t0 + c) * 33 + j] = f[c][d] + bias;
            }
        }
    }
    __syncthreads();

    // ---------------- Phase E: gated update + layernorm ----------------
    {
        const float eta = 1.f / (1.f + __expf(-__ldg(eta_logit)));
        const int s = lane >> 4;
        const int j = lane & 15;
        #pragma unroll
        for (int p = 0; p < 2; p++) {
            int t = (wid << 2) + (p << 1) + s;
            float gp = sgc[t * 33 + j];
            float cp = sgc[t * 33 + 16 + j];
            float eg = eta * (1.f / (1.f + __expf(-gp)));
            float val = (1.f - eg) * shx[t * XS + j] + eg * tanhf(cp);
            float sum = val;
            #pragma unroll
            for (int msk = 8; msk > 0; msk >>= 1)
                sum += __shfl_xor_sync(0xffffffffu, sum, msk, 16);
            float mu = sum * (1.f / 16.f);
            float dv = val - mu;
            float vs = dv * dv;
            #pragma unroll
            for (int msk = 8; msk > 0; msk >>= 1)
                vs += __shfl_xor_sync(0xffffffffu, vs, msk, 16);
            float var = vs * (1.f / 16.f);
            out_z[(size_t)(b * NN + t) * 16 + j] = dv * rsqrtf(var + 1e-5f);
        }
    }
}

extern "C" void kernel_launch(void* const* d_in, const int* in_sizes, int n_in,
                              void* d_out, int out_size) {
    const float* h        = (const float*)d_in[0];
    const float* u        = (const float*)d_in[1];
    const float* z        = (const float*)d_in[2];
    const float* qd_down  = (const float*)d_in[3];
    const float* qd_up    = (const float*)d_in[4];
    const float* kd_down  = (const float*)d_in[5];
    const float* kd_up    = (const float*)d_in[6];
    const float* vd_down  = (const float*)d_in[7];
    const float* vd_up    = (const float*)d_in[8];
    const float* od_down  = (const float*)d_in[9];
    const float* od_up    = (const float*)d_in[10];
    const float* ug_w     = (const float*)d_in[11];
    const float* ug_b     = (const float*)d_in[12];
    const float* cand_w   = (const float*)d_in[13];
    const float* cand_b   = (const float*)d_in[14];
    const float* eta_logit= (const float*)d_in[15];

    float* o = (float*)d_out;
    float* out_c    = o;                        // 4096*64*128
    float* out_z    = o + (size_t)33554432;     // 4096*64*16
    float* out_attn = o + (size_t)37748736;     // 4096*64*64
    float* out_q    = o + (size_t)54525952;
    float* out_k    = o + (size_t)71303168;
    float* out_v    = o + (size_t)88080384;

    const int smem_bytes = SMEM_FLOATS * sizeof(float);  // 225280
    cudaFuncSetAttribute(memetic_fused_kernel,
                         cudaFuncAttributeMaxDynamicSharedMemorySize, smem_bytes);

    memetic_fused_kernel<<<BB, 512, smem_bytes>>>(
        h, u, z, qd_down, qd_up, kd_down, kd_up, vd_down, vd_up,
        od_down, od_up, ug_w, ug_b, cand_w, cand_b, eta_logit,
        out_c, out_z, out_attn, out_q, out_k, out_v);
}

// round 5
// speedup vs baseline: 1.9052x; 1.9052x over previous
#include <cuda_runtime.h>
#include <math.h>

#define BB 4096
#define NN 64

// smem layout (floats):
//  sh_h [64][260] = 16640   (260 % 8 == 4 -> conflict-free float4 rows at delta-8 tokens)
//  sh_z [64][20]  = 1280    (20 % 8 == 4)
//  sh_c [64][132] = 8448    (132 % 8 == 4)
//  swc  [400][32] = 12800   (cols 0..15 gate, 16..31 cand)
//  sq   [64][68]  = 4352    q row-major
//  skT  [64][68]  = 4352    k transposed [d][t]   (alias: clat after C1)
//  sv   [64][68]  = 4352    v row-major
//  sat  [64][68]  = 4352    scores/attn           (alias: gate/cand after C2)
#define OFF_H   0
#define OFF_Z   16640
#define OFF_C   17920
#define OFF_WC  26368
#define OFF_Q   39168
#define OFF_KT  43520
#define OFF_V   47872
#define OFF_AT  52224
#define SMEM_FLOATS 56576

typedef unsigned long long ull;

__device__ __forceinline__ ull pk(float a, float b) {
    ull r; asm("mov.b64 %0, {%1, %2};" : "=l"(r) : "f"(a), "f"(b)); return r;
}
__device__ __forceinline__ void upk(ull v, float& a, float& b) {
    asm("mov.b64 {%0, %1}, %2;" : "=f"(a), "=f"(b) : "l"(v));
}
#define FMAX2(acc, a, b) asm("fma.rn.f32x2 %0, %1, %2, %0;" : "+l"(acc) : "l"(a), "l"(b))

__device__ __forceinline__ float wsum32(float v) {
    #pragma unroll
    for (int m = 16; m > 0; m >>= 1) v += __shfl_xor_sync(0xffffffffu, v, m);
    return v;
}
__device__ __forceinline__ float wmax32(float v) {
    #pragma unroll
    for (int m = 16; m > 0; m >>= 1) v = fmaxf(v, __shfl_xor_sync(0xffffffffu, v, m));
    return v;
}

// Phase-D inner: 4 tokens (delta-8 rows) x 16 outputs over n4*4 k-rows.
__device__ __forceinline__ void d_accum(const float* __restrict__ x0, int xs,
                                        const float* __restrict__ w, int ibase,
                                        int n4, int j0, ull acc[4][2]) {
    for (int s = 0; s < n4; s++) {
        const int il = s << 2;
        float4 x4[4];
        #pragma unroll
        for (int c = 0; c < 4; c++)
            x4[c] = *reinterpret_cast<const float4*>(x0 + c * 8 * xs + il);
        const float* wr = w + (ibase + il) * 32 + j0;
        #pragma unroll
        for (int r = 0; r < 4; r++) {
            float4 w4 = *reinterpret_cast<const float4*>(wr + r * 32);
            ull wlo = pk(w4.x, w4.y), whi = pk(w4.z, w4.w);
            #pragma unroll
            for (int c = 0; c < 4; c++) {
                float xv = (r == 0) ? x4[c].x : (r == 1) ? x4[c].y : (r == 2) ? x4[c].z : x4[c].w;
                ull xd = pk(xv, xv);
                FMAX2(acc[c][0], xd, wlo);
                FMAX2(acc[c][1], xd, whi);
            }
        }
    }
}

__global__ __launch_bounds__(512, 1)
void memetic_fused_kernel(
    const float* __restrict__ h, const float* __restrict__ u, const float* __restrict__ z,
    const float* __restrict__ qd_down, const float* __restrict__ qd_up,
    const float* __restrict__ kd_down, const float* __restrict__ kd_up,
    const float* __restrict__ vd_down, const float* __restrict__ vd_up,
    const float* __restrict__ od_down, const float* __restrict__ od_up,
    const float* __restrict__ ug_w, const float* __restrict__ ug_b,
    const float* __restrict__ cand_w, const float* __restrict__ cand_b,
    const float* __restrict__ eta_logit,
    float* __restrict__ out_c, float* __restrict__ out_z,
    float* __restrict__ out_attn, float* __restrict__ out_q,
    float* __restrict__ out_k, float* __restrict__ out_v)
{
    extern __shared__ float sm[];
    float* sh_h = sm + OFF_H;
    float* sh_z = sm + OFF_Z;
    float* sh_c = sm + OFF_C;
    float* swc  = sm + OFF_WC;
    float* sq   = sm + OFF_Q;
    float* skT  = sm + OFF_KT;
    float* sv   = sm + OFF_V;
    float* sat  = sm + OFF_AT;
    float* sclat = skT;          // alias: kT dead after C1
    float* sred  = sq;           // alias: q(+kT) dead after C3 (needs 6144 fl)
    float* sgc   = sat;          // alias: at dead after C2

    const int b    = blockIdx.x;
    const int tid  = threadIdx.x;
    const int wid  = tid >> 5;
    const int lane = tid & 31;
    const float NEG_INF = __int_as_float(0xff800000);

    // ---------------- Phase A: stage h, z, gate weights ----------------
    {
        const float4* hb4 = reinterpret_cast<const float4*>(h + (size_t)b * (NN * 256));
        #pragma unroll
        for (int c = 0; c < 4; c++) {
            int row = (wid << 2) + c;
            #pragma unroll
            for (int it = 0; it < 2; it++) {
                int c4 = lane + (it << 5);
                float4 v4 = hb4[row * 64 + c4];
                *reinterpret_cast<float4*>(sh_h + row * 260 + (c4 << 2)) = v4;
            }
        }
        const float* zb = z + (size_t)b * (NN * 16);
        for (int i = tid; i < NN * 16; i += 512)
            sh_z[(i >> 4) * 20 + (i & 15)] = zb[i];
        const float4* ug4 = reinterpret_cast<const float4*>(ug_w);
        const float4* cd4 = reinterpret_cast<const float4*>(cand_w);
        float4* wc4 = reinterpret_cast<float4*>(swc);
        for (int i4 = tid; i4 < 3200; i4 += 512) {
            int r = i4 >> 3, jq = i4 & 7;
            wc4[i4] = (jq < 4) ? __ldg(ug4 + r * 4 + jq) : __ldg(cd4 + r * 4 + (jq - 4));
        }
    }
    __syncthreads();

    // ---------------- Phase B: q, k, v (warp per token, 4 tokens/warp) ----------------
    {
        const float* ub = u + (size_t)b * (NN * 128);
        const float4* qdd4 = reinterpret_cast<const float4*>(qd_down);
        const float4* kdd4 = reinterpret_cast<const float4*>(kd_down);
        const float4* vdd4 = reinterpret_cast<const float4*>(vd_down);
        for (int c0 = 0; c0 < 4; c0++) {
            const int t = (wid << 2) + c0;
            float q0 = 0.f, q1 = 0.f, q2 = 0.f, q3 = 0.f;
            for (int i = lane; i < 272; i += 32) {
                float x = (i < 256) ? sh_h[t * 260 + i] : sh_z[t * 20 + (i - 256)];
                float4 wv = __ldg(qdd4 + i);
                q0 += x * wv.x; q1 += x * wv.y; q2 += x * wv.z; q3 += x * wv.w;
            }
            q0 = wsum32(q0); q1 = wsum32(q1); q2 = wsum32(q2); q3 = wsum32(q3);
            float k0 = 0.f, k1 = 0.f, k2 = 0.f, k3 = 0.f;
            float v0 = 0.f, v1 = 0.f, v2 = 0.f, v3 = 0.f;
            #pragma unroll
            for (int it = 0; it < 4; it++) {
                int i = lane + it * 32;
                float x = __ldg(ub + t * 128 + i);
                float4 kw = __ldg(kdd4 + i);
                float4 vw = __ldg(vdd4 + i);
                k0 += x * kw.x; k1 += x * kw.y; k2 += x * kw.z; k3 += x * kw.w;
                v0 += x * vw.x; v1 += x * vw.y; v2 += x * vw.z; v3 += x * vw.w;
            }
            k0 = wsum32(k0); k1 = wsum32(k1); k2 = wsum32(k2); k3 = wsum32(k3);
            v0 = wsum32(v0); v1 = wsum32(v1); v2 = wsum32(v2); v3 = wsum32(v3);
            const size_t tok = (size_t)(b * NN + t);
            #pragma unroll
            for (int s = 0; s < 2; s++) {
                int d = lane + (s << 5);
                float qv = 0.25f * (q0 * __ldg(qd_up + d)       + q1 * __ldg(qd_up + 64 + d)
                                  + q2 * __ldg(qd_up + 128 + d) + q3 * __ldg(qd_up + 192 + d));
                float kv = 0.25f * (k0 * __ldg(kd_up + d)       + k1 * __ldg(kd_up + 64 + d)
                                  + k2 * __ldg(kd_up + 128 + d) + k3 * __ldg(kd_up + 192 + d));
                float vv = 0.25f * (v0 * __ldg(vd_up + d)       + v1 * __ldg(vd_up + 64 + d)
                                  + v2 * __ldg(vd_up + 128 + d) + v3 * __ldg(vd_up + 192 + d));
                sq[t * 68 + d]  = qv;
                skT[d * 68 + t] = kv;
                sv[t * 68 + d]  = vv;
                out_q[tok * 64 + d] = qv;
                out_k[tok * 64 + d] = kv;
                out_v[tok * 64 + d] = vv;
            }
        }
    }
    __syncthreads();

    // ---------------- Phase C1: QK scores (R3 tiling + f32x2) ----------------
    {
        const int nb = wid >> 1, mh = wid & 1;
        const int np = lane & 3, mg = lane >> 2;
        const int n0 = nb * 8 + np * 2;
        const int m0 = mh * 32 + mg * 4;
        ull a0lo = 0ull, a0hi = 0ull, a1lo = 0ull, a1hi = 0ull;
        #pragma unroll 8
        for (int d = 0; d < 64; d++) {
            float q0 = sq[n0 * 68 + d];
            float q1 = sq[(n0 + 1) * 68 + d];
            float4 kq = *reinterpret_cast<const float4*>(skT + d * 68 + m0);
            ull klo = pk(kq.x, kq.y), khi = pk(kq.z, kq.w);
            ull q0d = pk(q0, q0), q1d = pk(q1, q1);
            FMAX2(a0lo, q0d, klo); FMAX2(a0hi, q0d, khi);
            FMAX2(a1lo, q1d, klo); FMAX2(a1hi, q1d, khi);
        }
        float s0x, s0y, s0z, s0w, s1x, s1y, s1z, s1w;
        upk(a0lo, s0x, s0y); upk(a0hi, s0z, s0w);
        upk(a1lo, s1x, s1y); upk(a1hi, s1z, s1w);
        const float rs = 0.125f;
        float4 r0 = make_float4(s0x * rs, s0y * rs, s0z * rs, s0w * rs);
        float4 r1 = make_float4(s1x * rs, s1y * rs, s1z * rs, s1w * rs);
        if (n0     == m0    ) r0.x = NEG_INF;
        if (n0     == m0 + 1) r0.y = NEG_INF;
        if (n0     == m0 + 2) r0.z = NEG_INF;
        if (n0     == m0 + 3) r0.w = NEG_INF;
        if (n0 + 1 == m0    ) r1.x = NEG_INF;
        if (n0 + 1 == m0 + 1) r1.y = NEG_INF;
        if (n0 + 1 == m0 + 2) r1.z = NEG_INF;
        if (n0 + 1 == m0 + 3) r1.w = NEG_INF;
        *reinterpret_cast<float4*>(sat + n0 * 68 + m0)       = r0;
        *reinterpret_cast<float4*>(sat + (n0 + 1) * 68 + m0) = r1;
    }
    __syncthreads();

    // ---------------- Phase C1b: softmax (warp per 4 rows) ----------------
    {
        #pragma unroll
        for (int rr = 0; rr < 4; rr++) {
            int n = (wid << 2) + rr;
            float s0 = sat[n * 68 + lane];
            float s1 = sat[n * 68 + lane + 32];
            float mx = wmax32(fmaxf(s0, s1));
            float e0 = __expf(s0 - mx), e1 = __expf(s1 - mx);
            float inv = 1.f / wsum32(e0 + e1);
            float a0 = e0 * inv, a1 = e1 * inv;
            sat[n * 68 + lane]      = a0;
            sat[n * 68 + lane + 32] = a1;
            size_t tk = (size_t)(b * NN + n) * 64;
            out_attn[tk + lane]      = a0;
            out_attn[tk + lane + 32] = a1;
        }
    }
    __syncthreads();

    // ---------------- Phase C2: c_latent = attn @ v (R3 tiling + f32x2) ----------------
    {
        const int nb = wid >> 1, dh = wid & 1;
        const int np = lane & 3, dg = lane >> 2;
        const int n0 = nb * 8 + np * 2;
        const int d0 = dh * 32 + dg * 4;
        ull c0lo = 0ull, c0hi = 0ull, c1lo = 0ull, c1hi = 0ull;
        #pragma unroll 8
        for (int m = 0; m < 64; m++) {
            float a0 = sat[n0 * 68 + m];
            float a1 = sat[(n0 + 1) * 68 + m];
            float4 v4 = *reinterpret_cast<const float4*>(sv + m * 68 + d0);
            ull vlo = pk(v4.x, v4.y), vhi = pk(v4.z, v4.w);
            ull a0d = pk(a0, a0), a1d = pk(a1, a1);
            FMAX2(c0lo, a0d, vlo); FMAX2(c0hi, a0d, vhi);
            FMAX2(c1lo, a1d, vlo); FMAX2(c1hi, a1d, vhi);
        }
        __syncthreads();   // kT reads done; safe to overwrite as clat
        float x0, x1, x2, x3;
        upk(c0lo, x0, x1); upk(c0hi, x2, x3);
        *reinterpret_cast<float4*>(sclat + n0 * 68 + d0) = make_float4(x0, x1, x2, x3);
        upk(c1lo, x0, x1); upk(c1hi, x2, x3);
        *reinterpret_cast<float4*>(sclat + (n0 + 1) * 68 + d0) = make_float4(x0, x1, x2, x3);
    }
    __syncthreads();

    // ---------------- Phase C3: rank-4 output projection (warp per token) ----------------
    {
        const float4* odd4 = reinterpret_cast<const float4*>(od_down);
        float4 o0 = __ldg(odd4 + lane);
        float4 o1 = __ldg(odd4 + lane + 32);
        for (int c0 = 0; c0 < 4; c0++) {
            int t = (wid << 2) + c0;
            float ca = sclat[t * 68 + lane];
            float cb = sclat[t * 68 + lane + 32];
            float r0 = wsum32(ca * o0.x + cb * o1.x);
            float r1 = wsum32(ca * o0.y + cb * o1.y);
            float r2 = wsum32(ca * o0.z + cb * o1.z);
            float r3 = wsum32(ca * o0.w + cb * o1.w);
            size_t tk = (size_t)(b * NN + t) * 128;
            #pragma unroll
            for (int s = 0; s < 4; s++) {
                int j = lane + (s << 5);
                float cv = 0.25f * (r0 * __ldg(od_up + j)       + r1 * __ldg(od_up + 128 + j)
                                  + r2 * __ldg(od_up + 256 + j) + r3 * __ldg(od_up + 384 + j));
                sh_c[t * 132 + j] = cv;
                out_c[tk + j] = cv;
            }
        }
    }
    __syncthreads();

    // ---------------- Phase D: gate/cand matmuls; conflict-free float4 + f32x2 ----------------
    // 4 tiles (32tok x 16out) x 4-warp k-split; thread: 4 tokens (delta 8) x 16 outs (j0..j0+3, j0+16? no: 4 j)
    {
        const int ip   = wid & 3;
        const int tile = wid >> 2;
        const int th   = tile >> 1;
        const int j0   = (tile & 1) * 16 + (lane >> 3) * 4;
        const int t0   = th * 32 + (lane & 7);
        ull acc[4][2];
        #pragma unroll
        for (int c = 0; c < 4; c++) { acc[c][0] = 0ull; acc[c][1] = 0ull; }
        const float* xh = sh_h + t0 * 260;
        const float* xz = sh_z + t0 * 20;
        const float* xc = sh_c + t0 * 132;
        if (ip == 0) {
            d_accum(xz, 20, swc, 0, 4, j0, acc);        // i 0..15
            d_accum(xh, 260, swc, 16, 21, j0, acc);     // i 16..99
        } else if (ip == 1) {
            d_accum(xh + 84, 260, swc, 100, 25, j0, acc);   // i 100..199
        } else if (ip == 2) {
            d_accum(xh + 184, 260, swc, 200, 18, j0, acc);  // i 200..271
            d_accum(xc, 132, swc, 272, 7, j0, acc);         // i 272..299
        } else {
            d_accum(xc + 28, 132, swc, 300, 25, j0, acc);   // i 300..399
        }
        float f[4][4];
        #pragma unroll
        for (int c = 0; c < 4; c++) {
            upk(acc[c][0], f[c][0], f[c][1]);
            upk(acc[c][1], f[c][2], f[c][3]);
        }
        __syncthreads();   // q/kT fully dead -> sred safe
        if (ip != 0) {
            float* dst = sred + (tile * 3 + (ip - 1)) * 512;
            #pragma unroll
            for (int c = 0; c < 4; c++)
                #pragma unroll
                for (int d = 0; d < 4; d++)
                    dst[(c * 4 + d) * 32 + lane] = f[c][d];
        }
        __syncthreads();
        if (ip == 0) {
            #pragma unroll
            for (int s = 0; s < 3; s++) {
                const float* src = sred + (tile * 3 + s) * 512;
                #pragma unroll
                for (int c = 0; c < 4; c++)
                    #pragma unroll
                    for (int d = 0; d < 4; d++)
                        f[c][d] += src[(c * 4 + d) * 32 + lane];
            }
            #pragma unroll
            for (int d = 0; d < 4; d++) {
                int j = j0 + d;
                float bias = (j < 16) ? __ldg(ug_b + j) : __ldg(cand_b + j - 16);
                #pragma unroll
                for (int c = 0; c < 4; c++)
                    sgc[(t0 + 8 * c) * 33 + j] = f[c][d] + bias;
            }
        }
    }
    __syncthreads();

    // ---------------- Phase E: gated update + layernorm ----------------
    {
        const float eta = 1.f / (1.f + __expf(-__ldg(eta_logit)));
        const int s = lane >> 4;
        const int j = lane & 15;
        #pragma unroll
        for (int p = 0; p < 2; p++) {
            int t = (wid << 2) + (p << 1) + s;
            float gp = sgc[t * 33 + j];
            float cp = sgc[t * 33 + 16 + j];
            float eg = eta * (1.f / (1.f + __expf(-gp)));
            float val = (1.f - eg) * sh_z[t * 20 + j] + eg * tanhf(cp);
            float sum = val;
            #pragma unroll
            for (int msk = 8; msk > 0; msk >>= 1)
                sum += __shfl_xor_sync(0xffffffffu, sum, msk, 16);
            float mu = sum * (1.f / 16.f);
            float dv = val - mu;
            float vs = dv * dv;
            #pragma unroll
            for (int msk = 8; msk > 0; msk >>= 1)
                vs += __shfl_xor_sync(0xffffffffu, vs, msk, 16);
            float var = vs * (1.f / 16.f);
            out_z[(size_t)(b * NN + t) * 16 + j] = dv * rsqrtf(var + 1e-5f);
        }
    }
}

extern "C" void kernel_launch(void* const* d_in, const int* in_sizes, int n_in,
                              void* d_out, int out_size) {
    const float* h        = (const float*)d_in[0];
    const float* u        = (const float*)d_in[1];
    const float* z        = (const float*)d_in[2];
    const float* qd_down  = (const float*)d_in[3];
    const float* qd_up    = (const float*)d_in[4];
    const float* kd_down  = (const float*)d_in[5];
    const float* kd_up    = (const float*)d_in[6];
    const float* vd_down  = (const float*)d_in[7];
    const float* vd_up    = (const float*)d_in[8];
    const float* od_down  = (const float*)d_in[9];
    const float* od_up    = (const float*)d_in[10];
    const float* ug_w     = (const float*)d_in[11];
    const float* ug_b     = (const float*)d_in[12];
    const float* cand_w   = (const float*)d_in[13];
    const float* cand_b   = (const float*)d_in[14];
    const float* eta_logit= (const float*)d_in[15];

    float* o = (float*)d_out;
    float* out_c    = o;                        // 4096*64*128
    float* out_z    = o + (size_t)33554432;     // 4096*64*16
    float* out_attn = o + (size_t)37748736;     // 4096*64*64
    float* out_q    = o + (size_t)54525952;
    float* out_k    = o + (size_t)71303168;
    float* out_v    = o + (size_t)88080384;

    const int smem_bytes = SMEM_FLOATS * sizeof(float);  // 226304
    cudaFuncSetAttribute(memetic_fused_kernel,
                         cudaFuncAttributeMaxDynamicSharedMemorySize, smem_bytes);

    memetic_fused_kernel<<<BB, 512, smem_bytes>>>(
        h, u, z, qd_down, qd_up, kd_down, kd_up, vd_down, vd_up,
        od_down, od_up, ug_w, ug_b, cand_w, cand_b, eta_logit,
        out_c, out_z, out_attn, out_q, out_k, out_v);
}

// round 6
// speedup vs baseline: 2.0186x; 1.0595x over previous
#include <cuda_runtime.h>
#include <math.h>

#define BB 4096
#define NN 64

// smem layout (floats):
//  sh_h [64][260] = 16640
//  sh_z [64][20]  = 1280
//  sh_c [64][132] = 8448
//  swc  [400][32] = 12800
//  sq   [64][68]  = 4352  q row-major   (alias: clat after C1)
//  sk   [64][68]  = 4352  k row-major   (alias: sred part1 in D)
//  sv   [64][68]  = 4352  v row-major   (alias: sred part2 in D)
//  sat  [64][68]  = 4352  scores/attn   (alias: gate/cand in D/E)
#define OFF_H   0
#define OFF_Z   16640
#define OFF_C   17920
#define OFF_WC  26368
#define OFF_Q   39168
#define OFF_K   43520
#define OFF_V   47872
#define OFF_AT  52224
#define SMEM_FLOATS 56576

typedef unsigned long long ull;

__device__ __forceinline__ ull pk(float a, float b) {
    ull r; asm("mov.b64 %0, {%1, %2};" : "=l"(r) : "f"(a), "f"(b)); return r;
}
__device__ __forceinline__ void upk(ull v, float& a, float& b) {
    asm("mov.b64 {%0, %1}, %2;" : "=f"(a), "=f"(b) : "l"(v));
}
#define FMAX2(acc, a, b) asm("fma.rn.f32x2 %0, %1, %2, %0;" : "+l"(acc) : "l"(a), "l"(b))

__device__ __forceinline__ float wsum32(float v) {
    #pragma unroll
    for (int m = 16; m > 0; m >>= 1) v += __shfl_xor_sync(0xffffffffu, v, m);
    return v;
}
__device__ __forceinline__ float wmax32(float v) {
    #pragma unroll
    for (int m = 16; m > 0; m >>= 1) v = fmaxf(v, __shfl_xor_sync(0xffffffffu, v, m));
    return v;
}

// Phase-D inner: 4 tokens (delta-8 rows) x 16 outputs over n4*4 k-rows.
__device__ __forceinline__ void d_accum(const float* __restrict__ x0, int xs,
                                        const float* __restrict__ w, int ibase,
                                        int n4, int j0, ull acc[4][2]) {
    for (int s = 0; s < n4; s++) {
        const int il = s << 2;
        float4 x4[4];
        #pragma unroll
        for (int c = 0; c < 4; c++)
            x4[c] = *reinterpret_cast<const float4*>(x0 + c * 8 * xs + il);
        const float* wr = w + (ibase + il) * 32 + j0;
        #pragma unroll
        for (int r = 0; r < 4; r++) {
            float4 w4 = *reinterpret_cast<const float4*>(wr + r * 32);
            ull wlo = pk(w4.x, w4.y), whi = pk(w4.z, w4.w);
            #pragma unroll
            for (int c = 0; c < 4; c++) {
                float xv = (r == 0) ? x4[c].x : (r == 1) ? x4[c].y : (r == 2) ? x4[c].z : x4[c].w;
                ull xd = pk(xv, xv);
                FMAX2(acc[c][0], xd, wlo);
                FMAX2(acc[c][1], xd, whi);
            }
        }
    }
}

__global__ __launch_bounds__(512, 1)
void memetic_fused_kernel(
    const float* __restrict__ h, const float* __restrict__ u, const float* __restrict__ z,
    const float* __restrict__ qd_down, const float* __restrict__ qd_up,
    const float* __restrict__ kd_down, const float* __restrict__ kd_up,
    const float* __restrict__ vd_down, const float* __restrict__ vd_up,
    const float* __restrict__ od_down, const float* __restrict__ od_up,
    const float* __restrict__ ug_w, const float* __restrict__ ug_b,
    const float* __restrict__ cand_w, const float* __restrict__ cand_b,
    const float* __restrict__ eta_logit,
    float* __restrict__ out_c, float* __restrict__ out_z,
    float* __restrict__ out_attn, float* __restrict__ out_q,
    float* __restrict__ out_k, float* __restrict__ out_v)
{
    extern __shared__ float sm[];
    float* sh_h = sm + OFF_H;
    float* sh_z = sm + OFF_Z;
    float* sh_c = sm + OFF_C;
    float* swc  = sm + OFF_WC;
    float* sq   = sm + OFF_Q;
    float* sk   = sm + OFF_K;
    float* sv   = sm + OFF_V;
    float* sat  = sm + OFF_AT;
    float* sclat = sq;           // alias: q dead after C1
    float* sred  = sk;           // alias: k dead after C1, v dead after C2 (6144 fl spans sk+sv)
    float* sgc   = sat;          // alias: at dead after C2

    const int b    = blockIdx.x;
    const int tid  = threadIdx.x;
    const int wid  = tid >> 5;
    const int lane = tid & 31;
    const float NEG_INF = __int_as_float(0xff800000);

    // ---------------- Phase A: stage h, z, gate weights ----------------
    {
        const float4* hb4 = reinterpret_cast<const float4*>(h + (size_t)b * (NN * 256));
        #pragma unroll
        for (int c = 0; c < 4; c++) {
            int row = (wid << 2) + c;
            #pragma unroll
            for (int it = 0; it < 2; it++) {
                int c4 = lane + (it << 5);
                float4 v4 = hb4[row * 64 + c4];
                *reinterpret_cast<float4*>(sh_h + row * 260 + (c4 << 2)) = v4;
            }
        }
        const float* zb = z + (size_t)b * (NN * 16);
        for (int i = tid; i < NN * 16; i += 512)
            sh_z[(i >> 4) * 20 + (i & 15)] = zb[i];
        const float4* ug4 = reinterpret_cast<const float4*>(ug_w);
        const float4* cd4 = reinterpret_cast<const float4*>(cand_w);
        float4* wc4 = reinterpret_cast<float4*>(swc);
        for (int i4 = tid; i4 < 3200; i4 += 512) {
            int r = i4 >> 3, jq = i4 & 7;
            wc4[i4] = (jq < 4) ? __ldg(ug4 + r * 4 + jq) : __ldg(cd4 + r * 4 + (jq - 4));
        }
    }
    __syncthreads();

    // ---------------- Phase B: q, k, v (warp per token, 4 tokens/warp) ----------------
    {
        const float* ub = u + (size_t)b * (NN * 128);
        const float4* qdd4 = reinterpret_cast<const float4*>(qd_down);
        const float4* kdd4 = reinterpret_cast<const float4*>(kd_down);
        const float4* vdd4 = reinterpret_cast<const float4*>(vd_down);
        // hoisted token-invariant weights
        float4 kw4[4], vw4[4];
        #pragma unroll
        for (int it = 0; it < 4; it++) {
            kw4[it] = __ldg(kdd4 + lane + it * 32);
            vw4[it] = __ldg(vdd4 + lane + it * 32);
        }
        float qu[8], ku[8], vu[8];
        #pragma unroll
        for (int r = 0; r < 4; r++) {
            #pragma unroll
            for (int s = 0; s < 2; s++) {
                int d = lane + (s << 5);
                qu[r * 2 + s] = __ldg(qd_up + r * 64 + d);
                ku[r * 2 + s] = __ldg(kd_up + r * 64 + d);
                vu[r * 2 + s] = __ldg(vd_up + r * 64 + d);
            }
        }
        for (int c0 = 0; c0 < 4; c0++) {
            const int t = (wid << 2) + c0;
            float q0 = 0.f, q1 = 0.f, q2 = 0.f, q3 = 0.f;
            for (int i = lane; i < 272; i += 32) {
                float x = (i < 256) ? sh_h[t * 260 + i] : sh_z[t * 20 + (i - 256)];
                float4 wv = __ldg(qdd4 + i);
                q0 += x * wv.x; q1 += x * wv.y; q2 += x * wv.z; q3 += x * wv.w;
            }
            q0 = wsum32(q0); q1 = wsum32(q1); q2 = wsum32(q2); q3 = wsum32(q3);
            float k0 = 0.f, k1 = 0.f, k2 = 0.f, k3 = 0.f;
            float v0 = 0.f, v1 = 0.f, v2 = 0.f, v3 = 0.f;
            #pragma unroll
            for (int it = 0; it < 4; it++) {
                float x = __ldg(ub + t * 128 + lane + it * 32);
                k0 += x * kw4[it].x; k1 += x * kw4[it].y; k2 += x * kw4[it].z; k3 += x * kw4[it].w;
                v0 += x * vw4[it].x; v1 += x * vw4[it].y; v2 += x * vw4[it].z; v3 += x * vw4[it].w;
            }
            k0 = wsum32(k0); k1 = wsum32(k1); k2 = wsum32(k2); k3 = wsum32(k3);
            v0 = wsum32(v0); v1 = wsum32(v1); v2 = wsum32(v2); v3 = wsum32(v3);
            const size_t tok = (size_t)(b * NN + t);
            #pragma unroll
            for (int s = 0; s < 2; s++) {
                int d = lane + (s << 5);
                float qv = 0.25f * (q0 * qu[s] + q1 * qu[2 + s] + q2 * qu[4 + s] + q3 * qu[6 + s]);
                float kv = 0.25f * (k0 * ku[s] + k1 * ku[2 + s] + k2 * ku[4 + s] + k3 * ku[6 + s]);
                float vv = 0.25f * (v0 * vu[s] + v1 * vu[2 + s] + v2 * vu[4 + s] + v3 * vu[6 + s]);
                sq[t * 68 + d] = qv;
                sk[t * 68 + d] = kv;
                sv[t * 68 + d] = vv;
                out_q[tok * 64 + d] = qv;
                out_k[tok * 64 + d] = kv;
                out_v[tok * 64 + d] = vv;
            }
        }
    }
    __syncthreads();

    // ---------------- Phase C1: QK scores; 16n x 32m tiles, thread 4x4, 2-warp d-split ----------------
    // rows n = nb+4a (nb = base+(lane&3)), cols m = mb+8bb (mb = base+(lane>>2)) -> all LDS conflict-free
    {
        const int tile = wid >> 1, ks = wid & 1;
        const int nb = ((tile >> 1) << 4) + (lane & 3);
        const int mb = ((tile & 1) << 5) + (lane >> 2);
        ull acc[4][4];
        #pragma unroll
        for (int a = 0; a < 4; a++)
            #pragma unroll
            for (int bb = 0; bb < 4; bb++) acc[a][bb] = 0ull;
        #pragma unroll
        for (int s = 0; s < 8; s++) {
            const int dd = (ks << 5) + (s << 2);
            float4 k4[4];
            ull klo[4], khi[4];
            #pragma unroll
            for (int bb = 0; bb < 4; bb++) {
                k4[bb] = *reinterpret_cast<const float4*>(sk + (mb + 8 * bb) * 68 + dd);
                klo[bb] = pk(k4[bb].x, k4[bb].y);
                khi[bb] = pk(k4[bb].z, k4[bb].w);
            }
            #pragma unroll
            for (int a = 0; a < 4; a++) {
                float4 q4 = *reinterpret_cast<const float4*>(sq + (nb + 4 * a) * 68 + dd);
                ull qlo = pk(q4.x, q4.y), qhi = pk(q4.z, q4.w);
                #pragma unroll
                for (int bb = 0; bb < 4; bb++) {
                    FMAX2(acc[a][bb], qlo, klo[bb]);
                    FMAX2(acc[a][bb], qhi, khi[bb]);
                }
            }
        }
        float sc[4][4];
        #pragma unroll
        for (int a = 0; a < 4; a++)
            #pragma unroll
            for (int bb = 0; bb < 4; bb++) {
                float lo, hi; upk(acc[a][bb], lo, hi); sc[a][bb] = lo + hi;
            }
        if (ks == 1) {
            #pragma unroll
            for (int a = 0; a < 4; a++)
                #pragma unroll
                for (int bb = 0; bb < 4; bb++)
                    sat[(nb + 4 * a) * 68 + mb + 8 * bb] = sc[a][bb];
        }
        __syncthreads();
        if (ks == 0) {
            #pragma unroll
            for (int a = 0; a < 4; a++) {
                const int n = nb + 4 * a;
                #pragma unroll
                for (int bb = 0; bb < 4; bb++) {
                    const int m = mb + 8 * bb;
                    float r = (sc[a][bb] + sat[n * 68 + m]) * 0.125f;
                    if (n == m) r = NEG_INF;
                    sat[n * 68 + m] = r;
                }
            }
        }
        __syncthreads();
    }

    // ---------------- Phase C1b: softmax (warp per 4 rows) ----------------
    {
        #pragma unroll
        for (int rr = 0; rr < 4; rr++) {
            int n = (wid << 2) + rr;
            float s0 = sat[n * 68 + lane];
            float s1 = sat[n * 68 + lane + 32];
            float mx = wmax32(fmaxf(s0, s1));
            float e0 = __expf(s0 - mx), e1 = __expf(s1 - mx);
            float inv = 1.f / wsum32(e0 + e1);
            float a0 = e0 * inv, a1 = e1 * inv;
            sat[n * 68 + lane]      = a0;
            sat[n * 68 + lane + 32] = a1;
            size_t tk = (size_t)(b * NN + n) * 64;
            out_attn[tk + lane]      = a0;
            out_attn[tk + lane + 32] = a1;
        }
    }
    __syncthreads();

    // ---------------- Phase C2: c_latent = attn @ v; same tiling, 2-warp m-split ----------------
    {
        const int tile = wid >> 1, ks = wid & 1;
        const int nb = ((tile >> 1) << 4) + (lane & 3);
        const int d0 = ((tile & 1) << 5) + ((lane >> 2) << 2);
        ull acc[4][2];
        #pragma unroll
        for (int a = 0; a < 4; a++) { acc[a][0] = 0ull; acc[a][1] = 0ull; }
        #pragma unroll
        for (int s = 0; s < 8; s++) {
            const int mm = (ks << 5) + (s << 2);
            ull vlo[4], vhi[4];
            #pragma unroll
            for (int t = 0; t < 4; t++) {
                float4 v4 = *reinterpret_cast<const float4*>(sv + (mm + t) * 68 + d0);
                vlo[t] = pk(v4.x, v4.y);
                vhi[t] = pk(v4.z, v4.w);
            }
            #pragma unroll
            for (int a = 0; a < 4; a++) {
                float4 a4 = *reinterpret_cast<const float4*>(sat + (nb + 4 * a) * 68 + mm);
                ull a0 = pk(a4.x, a4.x), a1 = pk(a4.y, a4.y);
                ull a2 = pk(a4.z, a4.z), a3 = pk(a4.w, a4.w);
                FMAX2(acc[a][0], a0, vlo[0]); FMAX2(acc[a][1], a0, vhi[0]);
                FMAX2(acc[a][0], a1, vlo[1]); FMAX2(acc[a][1], a1, vhi[1]);
                FMAX2(acc[a][0], a2, vlo[2]); FMAX2(acc[a][1], a2, vhi[2]);
                FMAX2(acc[a][0], a3, vlo[3]); FMAX2(acc[a][1], a3, vhi[3]);
            }
        }
        if (ks == 1) {
            #pragma unroll
            for (int a = 0; a < 4; a++) {
                float x0, x1, x2, x3;
                upk(acc[a][0], x0, x1); upk(acc[a][1], x2, x3);
                *reinterpret_cast<float4*>(sclat + (nb + 4 * a) * 68 + d0) =
                    make_float4(x0, x1, x2, x3);
            }
        }
        __syncthreads();
        if (ks == 0) {
            #pragma unroll
            for (int a = 0; a < 4; a++) {
                float4 p = *reinterpret_cast<const float4*>(sclat + (nb + 4 * a) * 68 + d0);
                float x0, x1, x2, x3;
                upk(acc[a][0], x0, x1); upk(acc[a][1], x2, x3);
                *reinterpret_cast<float4*>(sclat + (nb + 4 * a) * 68 + d0) =
                    make_float4(x0 + p.x, x1 + p.y, x2 + p.z, x3 + p.w);
            }
        }
        __syncthreads();
    }

    // ---------------- Phase C3: rank-4 output projection (warp per token) ----------------
    {
        const float4* odd4 = reinterpret_cast<const float4*>(od_down);
        float4 o0 = __ldg(odd4 + lane);
        float4 o1 = __ldg(odd4 + lane + 32);
        for (int c0 = 0; c0 < 4; c0++) {
            int t = (wid << 2) + c0;
            float ca = sclat[t * 68 + lane];
            float cb = sclat[t * 68 + lane + 32];
            float r0 = wsum32(ca * o0.x + cb * o1.x);
            float r1 = wsum32(ca * o0.y + cb * o1.y);
            float r2 = wsum32(ca * o0.z + cb * o1.z);
            float r3 = wsum32(ca * o0.w + cb * o1.w);
            size_t tk = (size_t)(b * NN + t) * 128;
            #pragma unroll
            for (int s = 0; s < 4; s++) {
                int j = lane + (s << 5);
                float cv = 0.25f * (r0 * __ldg(od_up + j)       + r1 * __ldg(od_up + 128 + j)
                                  + r2 * __ldg(od_up + 256 + j) + r3 * __ldg(od_up + 384 + j));
                sh_c[t * 132 + j] = cv;
                out_c[tk + j] = cv;
            }
        }
    }
    __syncthreads();

    // ---------------- Phase D: gate/cand matmuls; conflict-free float4 + f32x2 ----------------
    {
        const int ip   = wid & 3;
        const int tile = wid >> 2;
        const int th   = tile >> 1;
        const int j0   = (tile & 1) * 16 + (lane >> 3) * 4;
        const int t0   = th * 32 + (lane & 7);
        ull acc[4][2];
        #pragma unroll
        for (int c = 0; c < 4; c++) { acc[c][0] = 0ull; acc[c][1] = 0ull; }
        const float* xh = sh_h + t0 * 260;
        const float* xz = sh_z + t0 * 20;
        const float* xc = sh_c + t0 * 132;
        if (ip == 0) {
            d_accum(xz, 20, swc, 0, 4, j0, acc);
            d_accum(xh, 260, swc, 16, 21, j0, acc);
        } else if (ip == 1) {
            d_accum(xh + 84, 260, swc, 100, 25, j0, acc);
        } else if (ip == 2) {
            d_accum(xh + 184, 260, swc, 200, 18, j0, acc);
            d_accum(xc, 132, swc, 272, 7, j0, acc);
        } else {
            d_accum(xc + 28, 132, swc, 300, 25, j0, acc);
        }
        float f[4][4];
        #pragma unroll
        for (int c = 0; c < 4; c++) {
            upk(acc[c][0], f[c][0], f[c][1]);
            upk(acc[c][1], f[c][2], f[c][3]);
        }
        __syncthreads();   // k/v fully dead -> sred (spans sk+sv) safe
        if (ip != 0) {
            float* dst = sred + (tile * 3 + (ip - 1)) * 512;
            #pragma unroll
            for (int c = 0; c < 4; c++)
                #pragma unroll
                for (int d = 0; d < 4; d++)
                    dst[(c * 4 + d) * 32 + lane] = f[c][d];
        }
        __syncthreads();
        if (ip == 0) {
            #pragma unroll
            for (int s = 0; s < 3; s++) {
                const float* src = sred + (tile * 3 + s) * 512;
                #pragma unroll
                for (int c = 0; c < 4; c++)
                    #pragma unroll
                    for (int d = 0; d < 4; d++)
                        f[c][d] += src[(c * 4 + d) * 32 + lane];
            }
            #pragma unroll
            for (int d = 0; d < 4; d++) {
                int j = j0 + d;
                float bias = (j < 16) ? __ldg(ug_b + j) : __ldg(cand_b + j - 16);
                #pragma unroll
                for (int c = 0; c < 4; c++)
                    sgc[(t0 + 8 * c) * 33 + j] = f[c][d] + bias;
            }
        }
    }
    __syncthreads();

    // ---------------- Phase E: gated update + layernorm ----------------
    {
        const float eta = 1.f / (1.f + __expf(-__ldg(eta_logit)));
        const int s = lane >> 4;
        const int j = lane & 15;
        #pragma unroll
        for (int p = 0; p < 2; p++) {
            int t = (wid << 2) + (p << 1) + s;
            float gp = sgc[t * 33 + j];
            float cp = sgc[t * 33 + 16 + j];
            float eg = eta * (1.f / (1.f + __expf(-gp)));
            float val = (1.f - eg) * sh_z[t * 20 + j] + eg * tanhf(cp);
            float sum = val;
            #pragma unroll
            for (int msk = 8; msk > 0; msk >>= 1)
                sum += __shfl_xor_sync(0xffffffffu, sum, msk, 16);
            float mu = sum * (1.f / 16.f);
            float dv = val - mu;
            float vs = dv * dv;
            #pragma unroll
            for (int msk = 8; msk > 0; msk >>= 1)
                vs += __shfl_xor_sync(0xffffffffu, vs, msk, 16);
            float var = vs * (1.f / 16.f);
            out_z[(size_t)(b * NN + t) * 16 + j] = dv * rsqrtf(var + 1e-5f);
        }
    }
}

extern "C" void kernel_launch(void* const* d_in, const int* in_sizes, int n_in,
                              void* d_out, int out_size) {
    const float* h        = (const float*)d_in[0];
    const float* u        = (const float*)d_in[1];
    const float* z        = (const float*)d_in[2];
    const float* qd_down  = (const float*)d_in[3];
    const float* qd_up    = (const float*)d_in[4];
    const float* kd_down  = (const float*)d_in[5];
    const float* kd_up    = (const float*)d_in[6];
    const float* vd_down  = (const float*)d_in[7];
    const float* vd_up    = (const float*)d_in[8];
    const float* od_down  = (const float*)d_in[9];
    const float* od_up    = (const float*)d_in[10];
    const float* ug_w     = (const float*)d_in[11];
    const float* ug_b     = (const float*)d_in[12];
    const float* cand_w   = (const float*)d_in[13];
    const float* cand_b   = (const float*)d_in[14];
    const float* eta_logit= (const float*)d_in[15];

    float* o = (float*)d_out;
    float* out_c    = o;                        // 4096*64*128
    float* out_z    = o + (size_t)33554432;     // 4096*64*16
    float* out_attn = o + (size_t)37748736;     // 4096*64*64
    float* out_q    = o + (size_t)54525952;
    float* out_k    = o + (size_t)71303168;
    float* out_v    = o + (size_t)88080384;

    const int smem_bytes = SMEM_FLOATS * sizeof(float);  // 226304
    cudaFuncSetAttribute(memetic_fused_kernel,
                         cudaFuncAttributeMaxDynamicSharedMemorySize, smem_bytes);

    memetic_fused_kernel<<<BB, 512, smem_bytes>>>(
        h, u, z, qd_down, qd_up, kd_down, kd_up, vd_down, vd_up,
        od_down, od_up, ug_w, ug_b, cand_w, cand_b, eta_logit,
        out_c, out_z, out_attn, out_q, out_k, out_v);
}